// round 14
// baseline (speedup 1.0000x reference)
#include <cuda_runtime.h>
#include <cuda_fp16.h>
#include <cuda_bf16.h>
#include <cstdint>

// Problem constants
#define NN 100000
#define EE 1600000
#define DD 128
#define NB_SCAN ((NN + 255) / 256)   // 391 scan blocks

// ---------------- device scratch (no allocations allowed) ----------------
// g_deg/g_done zero on first use (CUDA zero-init), re-zeroed by k_scan_final.
__device__ int    g_done;
__device__ int    g_deg[NN];
__device__ int    g_rowptr[NN + 1];
__device__ int    g_cursor[NN];
__device__ int    g_psum[NB_SCAN];
__device__ __align__(16) int g_col[EE];   // edge payload: src node only
__device__ float  g_dinv[NN];
__device__ __half g_h1[NN * DD];     // dinv-scaled GEMM1 output
__device__ __half g_a1[NN * DD];     // layer-1 activation
__device__ __half g_h2[NN * DD];     // dinv-scaled GEMM2 output

// ---------------- helpers ----------------
__device__ __forceinline__ int load_idx(const void* ei, int pos, int is64) {
    if (is64) return (int)((const long long*)ei)[pos];
    return ((const int*)ei)[pos];
}

__device__ __forceinline__ int detect_is64(const int* ei32) {
    __shared__ int s_is64;
    if (threadIdx.x == 0) {
        int zeros = 0;
#pragma unroll
        for (int j = 0; j < 64; j++)
            if (ei32[2 * j + 1] == 0) zeros++;
        s_is64 = (zeros >= 60) ? 1 : 0;
    }
    __syncthreads();
    return s_is64;
}

// ---------------- graph-build kernels ----------------

// count degrees; return value unused -> REDG.
__global__ void k_count(const void* __restrict__ ei, int E) {
    int is64 = detect_is64((const int*)ei);
    int i = blockIdx.x * blockDim.x + threadIdx.x;
    if (!is64 && (E & 3) == 0) {
        int base = 4 * i;
        if (base >= E) return;
        const int4* dst4 = (const int4*)((const int*)ei + E);
        int4 d = dst4[i];
        if ((unsigned)d.x < (unsigned)NN) atomicAdd(&g_deg[d.x], 1);
        if ((unsigned)d.y < (unsigned)NN) atomicAdd(&g_deg[d.y], 1);
        if ((unsigned)d.z < (unsigned)NN) atomicAdd(&g_deg[d.z], 1);
        if ((unsigned)d.w < (unsigned)NN) atomicAdd(&g_deg[d.w], 1);
    } else {
        if (i >= E) return;
        int d = load_idx(ei, E + i, is64);
        if ((unsigned)d < (unsigned)NN) atomicAdd(&g_deg[d], 1);
    }
}

// Per-block sums -> g_psum[b]; LAST block scans g_psum (exclusive).
__global__ void k_reduce() {
    __shared__ int ws[8];
    __shared__ int s_last;
    int b = blockIdx.x, t = threadIdx.x;
    int lane = t & 31, w = t >> 5;
    int i = b * 256 + t;
    int v = (i < NN) ? g_deg[i] : 0;
#pragma unroll
    for (int off = 16; off > 0; off >>= 1)
        v += __shfl_xor_sync(0xFFFFFFFFu, v, off);
    if (lane == 0) ws[w] = v;
    __syncthreads();
    if (t == 0) {
        int s = 0;
#pragma unroll
        for (int k = 0; k < 8; k++) s += ws[k];
        g_psum[b] = s;
        __threadfence();
        int done = atomicAdd(&g_done, 1);
        s_last = (done == gridDim.x - 1) ? 1 : 0;
    }
    __syncthreads();
    if (!s_last) return;

    __shared__ int wsum[8];
    __shared__ int carry;
    if (t == 0) carry = 0;
    __syncthreads();
    for (int base = 0; base < NB_SCAN; base += 256) {
        int x = (base + t < NB_SCAN) ? g_psum[base + t] : 0;
        int s = x;
#pragma unroll
        for (int off = 1; off < 32; off <<= 1) {
            int u = __shfl_up_sync(0xFFFFFFFFu, s, off);
            if (lane >= off) s += u;
        }
        if (lane == 31) wsum[w] = s;
        __syncthreads();
        if (w == 0 && lane < 8) {
            int y = wsum[lane];
#pragma unroll
            for (int off = 1; off < 8; off <<= 1) {
                int u = __shfl_up_sync(0xFFu, y, off);
                if (lane >= off) y += u;
            }
            wsum[lane] = y;
        }
        __syncthreads();
        int pre = (w > 0) ? wsum[w - 1] : 0;
        int c = carry;
        if (base + t < NB_SCAN) g_psum[base + t] = c + pre + s - x;
        __syncthreads();
        if (t == 0) carry = c + wsum[7];
        __syncthreads();
    }
}

// Block-local scan + psum offset -> rowptr AND cursor; dinv fused;
// re-zero deg/done for next call.
__global__ void k_scan_final() {
    __shared__ int wsum[8];
    int b = blockIdx.x, t = threadIdx.x;
    int lane = t & 31, w = t >> 5;
    int i = b * 256 + t;
    int v = 0;
    if (i < NN) {
        v = g_deg[i];
        g_dinv[i] = rsqrtf((float)v + 1.0f);
        g_deg[i] = 0;
    }
    if (b == 0 && t == 0) g_done = 0;
    int s = v;
#pragma unroll
    for (int off = 1; off < 32; off <<= 1) {
        int u = __shfl_up_sync(0xFFFFFFFFu, s, off);
        if (lane >= off) s += u;
    }
    if (lane == 31) wsum[w] = s;
    __syncthreads();
    if (w == 0 && lane < 8) {
        int ws = wsum[lane];
#pragma unroll
        for (int off = 1; off < 8; off <<= 1) {
            int u = __shfl_up_sync(0xFFu, ws, off);
            if (lane >= off) ws += u;
        }
        wsum[lane] = ws;
    }
    __syncthreads();
    int pre = (w > 0) ? wsum[w - 1] : 0;
    int base = g_psum[b];
    if (i < NN) {
        g_rowptr[i + 1] = base + pre + s;
        g_cursor[i] = base + pre + s - v;
    }
    if (b == 0 && t == 0) g_rowptr[0] = 0;
}

// cursor scatter: one random atomic + one 4B random store per edge.
__device__ __forceinline__ void scatter_one(int s, int d) {
    if ((unsigned)s >= (unsigned)NN || (unsigned)d >= (unsigned)NN) return;
    int idx = atomicAdd(&g_cursor[d], 1);
    g_col[idx] = s;
}

__global__ void k_scatter(const void* __restrict__ ei, int E) {
    int is64 = detect_is64((const int*)ei);
    int i = blockIdx.x * blockDim.x + threadIdx.x;
    if (!is64 && (E & 3) == 0) {
        int base = 4 * i;
        if (base >= E) return;
        const int4* src4 = (const int4*)((const int*)ei);
        const int4* dst4 = (const int4*)((const int*)ei + E);
        int4 s = src4[i];
        int4 d = dst4[i];
        scatter_one(s.x, d.x);
        scatter_one(s.y, d.y);
        scatter_one(s.z, d.z);
        scatter_one(s.w, d.w);
    } else {
        if (i >= E) return;
        int s = load_idx(ei, i, is64);
        int d = load_idx(ei, E + i, is64);
        scatter_one(s, d);
    }
}

// ---------------- tensor-core GEMM (epilogue scales row by dinv) ----------
#define SRS 136

__device__ __forceinline__ void stage_wt(const float* __restrict__ Wm,
                                         __half* sBT, int tid) {
#pragma unroll
    for (int i = 0; i < 64; i++) {
        int idx = tid + 256 * i;
        int k = idx >> 7, nn = idx & 127;
        sBT[nn * SRS + k] = __float2half(Wm[idx]);
    }
}

__device__ __forceinline__ void gemm_tile(const __half* sA, const __half* sBT,
                                          __half* __restrict__ out, int row0,
                                          int n, int tid,
                                          const float* __restrict__ dinv) {
    int lane = tid & 31, warp = tid >> 5;
    int g = lane >> 2, tg = lane & 3;
    int rb = warp * 16;

    float acc[16][4];
#pragma unroll
    for (int nt = 0; nt < 16; nt++)
#pragma unroll
        for (int q = 0; q < 4; q++) acc[nt][q] = 0.f;

#pragma unroll
    for (int ks = 0; ks < 8; ks++) {
        int k0 = ks * 16;
        uint32_t a0 = *(const uint32_t*)(sA + (rb + g) * SRS + k0 + tg * 2);
        uint32_t a1 = *(const uint32_t*)(sA + (rb + g + 8) * SRS + k0 + tg * 2);
        uint32_t a2 = *(const uint32_t*)(sA + (rb + g) * SRS + k0 + 8 + tg * 2);
        uint32_t a3 = *(const uint32_t*)(sA + (rb + g + 8) * SRS + k0 + 8 + tg * 2);
#pragma unroll
        for (int nt = 0; nt < 16; nt++) {
            uint32_t b0 = *(const uint32_t*)(sBT + (nt * 8 + g) * SRS + k0 + tg * 2);
            uint32_t b1 = *(const uint32_t*)(sBT + (nt * 8 + g) * SRS + k0 + 8 + tg * 2);
            asm volatile(
                "mma.sync.aligned.m16n8k16.row.col.f32.f16.f16.f32 "
                "{%0,%1,%2,%3},{%4,%5,%6,%7},{%8,%9},{%0,%1,%2,%3};"
                : "+f"(acc[nt][0]), "+f"(acc[nt][1]),
                  "+f"(acc[nt][2]), "+f"(acc[nt][3])
                : "r"(a0), "r"(a1), "r"(a2), "r"(a3), "r"(b0), "r"(b1));
        }
    }

    int r1 = row0 + rb + g;
    int r2 = r1 + 8;
    float dv1 = (r1 < n) ? dinv[r1] : 0.f;
    float dv2 = (r2 < n) ? dinv[r2] : 0.f;
#pragma unroll
    for (int nt = 0; nt < 16; nt++) {
        int c = nt * 8 + tg * 2;
        if (r1 < n) {
            __half2 h = __floats2half2_rn(acc[nt][0] * dv1, acc[nt][1] * dv1);
            *(__half2*)(out + r1 * 128 + c) = h;
        }
        if (r2 < n) {
            __half2 h = __floats2half2_rn(acc[nt][2] * dv2, acc[nt][3] * dv2);
            *(__half2*)(out + r2 * 128 + c) = h;
        }
    }
}

template <bool HALF_IN>
__global__ void k_gemm_tc(const void* __restrict__ Ain, const float* __restrict__ Wm,
                          __half* __restrict__ out, const float* __restrict__ dinv,
                          int n) {
    extern __shared__ __half smh[];
    __half* sA = smh;
    __half* sBT = smh + 128 * SRS;
    int tid = threadIdx.x;
    int row0 = blockIdx.x * 128;

    stage_wt(Wm, sBT, tid);

    if (!HALF_IN) {
        const float4* A4 = (const float4*)Ain;
#pragma unroll
        for (int i = 0; i < 16; i++) {
            int idx = tid + 256 * i;
            int r = idx >> 5, c = (idx & 31) * 4;
            float4 v = make_float4(0.f, 0.f, 0.f, 0.f);
            if (row0 + r < n) v = A4[(row0 + r) * 32 + (idx & 31)];
            __half2 h0 = __floats2half2_rn(v.x, v.y);
            __half2 h1 = __floats2half2_rn(v.z, v.w);
            *(__half2*)(sA + r * SRS + c) = h0;
            *(__half2*)(sA + r * SRS + c + 2) = h1;
        }
    } else {
        const uint2* A2 = (const uint2*)Ain;
#pragma unroll
        for (int i = 0; i < 16; i++) {
            int idx = tid + 256 * i;
            int r = idx >> 5, c = (idx & 31) * 4;
            uint2 u = make_uint2(0u, 0u);
            if (row0 + r < n) u = A2[(row0 + r) * 32 + (idx & 31)];
            *(uint32_t*)(sA + r * SRS + c) = u.x;
            *(uint32_t*)(sA + r * SRS + c + 2) = u.y;
        }
    }
    __syncthreads();
    gemm_tile(sA, sBT, out, row0, n, tid, dinv);
}

// ---------------- aggregation: weightless row sums ----------------
// hs rows are pre-scaled by dinv[src] in the GEMM epilogue:
// out[d] = dinv[d] * ( sum_j hs[col_j] + hs[d] )
__device__ __forceinline__ void add_row(uint2 u, float& ax, float& ay,
                                        float& az, float& aw) {
    float2 p0 = __half22float2(*reinterpret_cast<__half2*>(&u.x));
    float2 p1 = __half22float2(*reinterpret_cast<__half2*>(&u.y));
    ax += p0.x; ay += p0.y; az += p1.x; aw += p1.y;
}

__device__ __forceinline__ void agg_row(const uint2* __restrict__ hin, int node,
                                        int lane, float& ax, float& ay,
                                        float& az, float& aw) {
    int j = g_rowptr[node];
    int e = g_rowptr[node + 1];
    float di = g_dinv[node];
    {
        uint2 u = hin[node * 32 + lane];
        float2 f0 = __half22float2(*reinterpret_cast<__half2*>(&u.x));
        float2 f1 = __half22float2(*reinterpret_cast<__half2*>(&u.y));
        ax = f0.x; ay = f0.y; az = f1.x; aw = f1.y;
    }
    // peel to 4-alignment for int4 meta loads
    while ((j & 3) && j < e) {
        add_row(hin[g_col[j] * 32 + lane], ax, ay, az, aw);
        j++;
    }
    for (; j + 7 < e; j += 8) {
        int4 c0 = *(const int4*)&g_col[j];
        int4 c1 = *(const int4*)&g_col[j + 4];
        uint2 u0 = hin[c0.x * 32 + lane];
        uint2 u1 = hin[c0.y * 32 + lane];
        uint2 u2 = hin[c0.z * 32 + lane];
        uint2 u3 = hin[c0.w * 32 + lane];
        uint2 u4 = hin[c1.x * 32 + lane];
        uint2 u5 = hin[c1.y * 32 + lane];
        uint2 u6 = hin[c1.z * 32 + lane];
        uint2 u7 = hin[c1.w * 32 + lane];
        add_row(u0, ax, ay, az, aw);
        add_row(u1, ax, ay, az, aw);
        add_row(u2, ax, ay, az, aw);
        add_row(u3, ax, ay, az, aw);
        add_row(u4, ax, ay, az, aw);
        add_row(u5, ax, ay, az, aw);
        add_row(u6, ax, ay, az, aw);
        add_row(u7, ax, ay, az, aw);
    }
    if (j + 3 < e) {
        int4 c0 = *(const int4*)&g_col[j];
        uint2 u0 = hin[c0.x * 32 + lane];
        uint2 u1 = hin[c0.y * 32 + lane];
        uint2 u2 = hin[c0.z * 32 + lane];
        uint2 u3 = hin[c0.w * 32 + lane];
        add_row(u0, ax, ay, az, aw);
        add_row(u1, ax, ay, az, aw);
        add_row(u2, ax, ay, az, aw);
        add_row(u3, ax, ay, az, aw);
        j += 4;
    }
    for (; j < e; j++)
        add_row(hin[g_col[j] * 32 + lane], ax, ay, az, aw);
    ax *= di; ay *= di; az *= di; aw *= di;
}

// MODE 0: +bias, ReLU, fp16 out.   MODE 1: +bias, LayerNorm, fp32 out.
template <int MODE>
__global__ void k_agg(const uint2* __restrict__ hin, void* __restrict__ outp,
                      const float* __restrict__ bias, const float* __restrict__ gamma,
                      const float* __restrict__ beta) {
    int gw = (blockIdx.x * blockDim.x + threadIdx.x) >> 5;
    int lane = threadIdx.x & 31;
    if (gw >= NN) return;
    float ax, ay, az, aw;
    agg_row(hin, gw, lane, ax, ay, az, aw);

    float4 bv = ((const float4*)bias)[lane];
    ax += bv.x; ay += bv.y; az += bv.z; aw += bv.w;

    if (MODE == 0) {
        __half2 h0 = __floats2half2_rn(fmaxf(ax, 0.f), fmaxf(ay, 0.f));
        __half2 h1 = __floats2half2_rn(fmaxf(az, 0.f), fmaxf(aw, 0.f));
        uint2 u;
        u.x = *reinterpret_cast<unsigned*>(&h0);
        u.y = *reinterpret_cast<unsigned*>(&h1);
        ((uint2*)outp)[gw * 32 + lane] = u;
    } else {
        float sum = ax + ay + az + aw;
#pragma unroll
        for (int off = 16; off > 0; off >>= 1)
            sum += __shfl_xor_sync(0xFFFFFFFFu, sum, off);
        float mu = sum * (1.0f / 128.0f);
        float dx = ax - mu, dy = ay - mu, dz = az - mu, dw = aw - mu;
        float sq = dx * dx + dy * dy + dz * dz + dw * dw;
#pragma unroll
        for (int off = 16; off > 0; off >>= 1)
            sq += __shfl_xor_sync(0xFFFFFFFFu, sq, off);
        float rstd = rsqrtf(sq * (1.0f / 128.0f) + 1e-5f);
        float4 gv = ((const float4*)gamma)[lane];
        float4 btv = ((const float4*)beta)[lane];
        float4 o;
        o.x = dx * rstd * gv.x + btv.x;
        o.y = dy * rstd * gv.y + btv.y;
        o.z = dz * rstd * gv.z + btv.z;
        o.w = dw * rstd * gv.w + btv.w;
        ((float4*)outp)[gw * 32 + lane] = o;
    }
}

// ---------------- launch ----------------
extern "C" void kernel_launch(void* const* d_in, const int* in_sizes, int n_in,
                              void* d_out, int out_size) {
    const float* x   = (const float*)d_in[0];
    const void*  ei  = d_in[1];
    const float* W1  = (const float*)d_in[2];
    const float* b1  = (const float*)d_in[3];
    const float* W2  = (const float*)d_in[4];
    const float* b2  = (const float*)d_in[5];
    const float* gm  = (const float*)d_in[6];
    const float* bt  = (const float*)d_in[7];
    float*       out = (float*)d_out;

    int E = in_sizes[1] / 2;

    __half* h1buf; cudaGetSymbolAddress((void**)&h1buf, g_h1);
    __half* a1buf; cudaGetSymbolAddress((void**)&a1buf, g_a1);
    __half* h2buf; cudaGetSymbolAddress((void**)&h2buf, g_h2);
    float* dinvp;  cudaGetSymbolAddress((void**)&dinvp, g_dinv);

    const size_t smem_gemm = 2 * 128 * SRS * sizeof(__half);  // 69632 B
    static bool s_init_done = false;
    static cudaStream_t s_side = nullptr;
    static cudaEvent_t ev_fork = nullptr, ev_join = nullptr;
    if (!s_init_done) {
        cudaFuncSetAttribute(k_gemm_tc<false>,
                             cudaFuncAttributeMaxDynamicSharedMemorySize, (int)smem_gemm);
        cudaFuncSetAttribute(k_gemm_tc<true>,
                             cudaFuncAttributeMaxDynamicSharedMemorySize, (int)smem_gemm);
        cudaStreamCreateWithFlags(&s_side, cudaStreamNonBlocking);
        cudaEventCreateWithFlags(&ev_fork, cudaEventDisableTiming);
        cudaEventCreateWithFlags(&ev_join, cudaEventDisableTiming);
        s_init_done = true;
    }

    int ebl4 = (E / 4 + 255) / 256;
    int ebl = (E + 255) / 256;
    int cnt_blocks = ((E & 3) == 0) ? ebl4 : ebl;
    int agg_blocks = (NN * 32 + 255) / 256;
    int gemm_blocks = (NN + 127) / 128;

    // ---- CSR build prefix (dinv ready after scan_final) ----
    k_count<<<cnt_blocks, 256>>>(ei, E);
    k_reduce<<<NB_SCAN, 256>>>();
    k_scan_final<<<NB_SCAN, 256>>>();

    // ---- fork: gemm1 (needs dinv) on side stream, overlaps scatter ----
    cudaEventRecord(ev_fork, 0);
    cudaStreamWaitEvent(s_side, ev_fork, 0);
    k_gemm_tc<false><<<gemm_blocks, 256, smem_gemm, s_side>>>(x, W1, h1buf, dinvp, NN);
    cudaEventRecord(ev_join, s_side);

    k_scatter<<<cnt_blocks, 256>>>(ei, E);

    // ---- join gemm1, then agg1 -> a1 ----
    cudaStreamWaitEvent(0, ev_join, 0);
    k_agg<0><<<agg_blocks, 256>>>((const uint2*)h1buf, a1buf, b1, nullptr, nullptr);

    // ---- gemm2: hs2 = dinv * (a1@W2) ----
    k_gemm_tc<true><<<gemm_blocks, 256, smem_gemm>>>(a1buf, W2, h2buf, dinvp, NN);

    // ---- agg2 + LayerNorm -> out ----
    k_agg<1><<<agg_blocks, 256>>>((const uint2*)h2buf, out, b2, gm, bt);
}

// round 15
// speedup vs baseline: 1.1045x; 1.1045x over previous
#include <cuda_runtime.h>
#include <cuda_fp16.h>
#include <cuda_bf16.h>
#include <cstdint>

// Problem constants
#define NN 100000
#define EE 1600000
#define DD 128
#define NB_SCAN ((NN + 255) / 256)   // 391 scan blocks

// ---------------- device scratch (no allocations allowed) ----------------
// g_deg/g_done zero on first use (CUDA zero-init), re-zeroed by k_scan_final.
__device__ int    g_done;
__device__ int    g_deg[NN];
__device__ int    g_rowptr[NN + 1];
__device__ int    g_cursor[NN];
__device__ int    g_psum[NB_SCAN];
__device__ __align__(16) int g_col[EE];   // edge payload: src node only
__device__ float  g_dinv[NN];
__device__ __half g_h1[NN * DD];     // GEMM1 output, then dinv-scaled in place
__device__ __half g_a1[NN * DD];     // layer-1 activation
__device__ __half g_h2[NN * DD];     // dinv-scaled GEMM2 output

// ---------------- helpers ----------------
__device__ __forceinline__ int load_idx(const void* ei, int pos, int is64) {
    if (is64) return (int)((const long long*)ei)[pos];
    return ((const int*)ei)[pos];
}

__device__ __forceinline__ int detect_is64(const int* ei32) {
    __shared__ int s_is64;
    if (threadIdx.x == 0) {
        int zeros = 0;
#pragma unroll
        for (int j = 0; j < 64; j++)
            if (ei32[2 * j + 1] == 0) zeros++;
        s_is64 = (zeros >= 60) ? 1 : 0;
    }
    __syncthreads();
    return s_is64;
}

// ---------------- graph-build kernels ----------------

// count degrees; return value unused -> REDG.
__global__ void k_count(const void* __restrict__ ei, int E) {
    int is64 = detect_is64((const int*)ei);
    int i = blockIdx.x * blockDim.x + threadIdx.x;
    if (!is64 && (E & 3) == 0) {
        int base = 4 * i;
        if (base >= E) return;
        const int4* dst4 = (const int4*)((const int*)ei + E);
        int4 d = dst4[i];
        if ((unsigned)d.x < (unsigned)NN) atomicAdd(&g_deg[d.x], 1);
        if ((unsigned)d.y < (unsigned)NN) atomicAdd(&g_deg[d.y], 1);
        if ((unsigned)d.z < (unsigned)NN) atomicAdd(&g_deg[d.z], 1);
        if ((unsigned)d.w < (unsigned)NN) atomicAdd(&g_deg[d.w], 1);
    } else {
        if (i >= E) return;
        int d = load_idx(ei, E + i, is64);
        if ((unsigned)d < (unsigned)NN) atomicAdd(&g_deg[d], 1);
    }
}

// Per-block sums -> g_psum[b]; LAST block scans g_psum (exclusive).
__global__ void k_reduce() {
    __shared__ int ws[8];
    __shared__ int s_last;
    int b = blockIdx.x, t = threadIdx.x;
    int lane = t & 31, w = t >> 5;
    int i = b * 256 + t;
    int v = (i < NN) ? g_deg[i] : 0;
#pragma unroll
    for (int off = 16; off > 0; off >>= 1)
        v += __shfl_xor_sync(0xFFFFFFFFu, v, off);
    if (lane == 0) ws[w] = v;
    __syncthreads();
    if (t == 0) {
        int s = 0;
#pragma unroll
        for (int k = 0; k < 8; k++) s += ws[k];
        g_psum[b] = s;
        __threadfence();
        int done = atomicAdd(&g_done, 1);
        s_last = (done == gridDim.x - 1) ? 1 : 0;
    }
    __syncthreads();
    if (!s_last) return;

    __shared__ int wsum[8];
    __shared__ int carry;
    if (t == 0) carry = 0;
    __syncthreads();
    for (int base = 0; base < NB_SCAN; base += 256) {
        int x = (base + t < NB_SCAN) ? g_psum[base + t] : 0;
        int s = x;
#pragma unroll
        for (int off = 1; off < 32; off <<= 1) {
            int u = __shfl_up_sync(0xFFFFFFFFu, s, off);
            if (lane >= off) s += u;
        }
        if (lane == 31) wsum[w] = s;
        __syncthreads();
        if (w == 0 && lane < 8) {
            int y = wsum[lane];
#pragma unroll
            for (int off = 1; off < 8; off <<= 1) {
                int u = __shfl_up_sync(0xFFu, y, off);
                if (lane >= off) y += u;
            }
            wsum[lane] = y;
        }
        __syncthreads();
        int pre = (w > 0) ? wsum[w - 1] : 0;
        int c = carry;
        if (base + t < NB_SCAN) g_psum[base + t] = c + pre + s - x;
        __syncthreads();
        if (t == 0) carry = c + wsum[7];
        __syncthreads();
    }
}

// Block-local scan + psum offset -> rowptr AND cursor; dinv fused;
// re-zero deg/done for next call.
__global__ void k_scan_final() {
    __shared__ int wsum[8];
    int b = blockIdx.x, t = threadIdx.x;
    int lane = t & 31, w = t >> 5;
    int i = b * 256 + t;
    int v = 0;
    if (i < NN) {
        v = g_deg[i];
        g_dinv[i] = rsqrtf((float)v + 1.0f);
        g_deg[i] = 0;
    }
    if (b == 0 && t == 0) g_done = 0;
    int s = v;
#pragma unroll
    for (int off = 1; off < 32; off <<= 1) {
        int u = __shfl_up_sync(0xFFFFFFFFu, s, off);
        if (lane >= off) s += u;
    }
    if (lane == 31) wsum[w] = s;
    __syncthreads();
    if (w == 0 && lane < 8) {
        int ws = wsum[lane];
#pragma unroll
        for (int off = 1; off < 8; off <<= 1) {
            int u = __shfl_up_sync(0xFFu, ws, off);
            if (lane >= off) ws += u;
        }
        wsum[lane] = ws;
    }
    __syncthreads();
    int pre = (w > 0) ? wsum[w - 1] : 0;
    int base = g_psum[b];
    if (i < NN) {
        g_rowptr[i + 1] = base + pre + s;
        g_cursor[i] = base + pre + s - v;
    }
    if (b == 0 && t == 0) g_rowptr[0] = 0;
}

// cursor scatter: one random atomic + one 4B random store per edge.
__device__ __forceinline__ void scatter_one(int s, int d) {
    if ((unsigned)s >= (unsigned)NN || (unsigned)d >= (unsigned)NN) return;
    int idx = atomicAdd(&g_cursor[d], 1);
    g_col[idx] = s;
}

__global__ void k_scatter(const void* __restrict__ ei, int E) {
    int is64 = detect_is64((const int*)ei);
    int i = blockIdx.x * blockDim.x + threadIdx.x;
    if (!is64 && (E & 3) == 0) {
        int base = 4 * i;
        if (base >= E) return;
        const int4* src4 = (const int4*)((const int*)ei);
        const int4* dst4 = (const int4*)((const int*)ei + E);
        int4 s = src4[i];
        int4 d = dst4[i];
        scatter_one(s.x, d.x);
        scatter_one(s.y, d.y);
        scatter_one(s.z, d.z);
        scatter_one(s.w, d.w);
    } else {
        if (i >= E) return;
        int s = load_idx(ei, i, is64);
        int d = load_idx(ei, E + i, is64);
        scatter_one(s, d);
    }
}

// scale h rows in place by dinv[row]: h[i,:] *= dinv[i]. 4 halves/thread.
__global__ void k_scale(__half* __restrict__ h) {
    int idx = blockIdx.x * blockDim.x + threadIdx.x;   // uint2 index
    if (idx >= NN * 32) return;
    float dv = g_dinv[idx >> 5];
    uint2 u = ((const uint2*)h)[idx];
    float2 f0 = __half22float2(*reinterpret_cast<__half2*>(&u.x));
    float2 f1 = __half22float2(*reinterpret_cast<__half2*>(&u.y));
    __half2 h0 = __floats2half2_rn(f0.x * dv, f0.y * dv);
    __half2 h1 = __floats2half2_rn(f1.x * dv, f1.y * dv);
    uint2 o;
    o.x = *reinterpret_cast<unsigned*>(&h0);
    o.y = *reinterpret_cast<unsigned*>(&h1);
    ((uint2*)h)[idx] = o;
}

// ---------------- tensor-core GEMM ----------------
#define SRS 136

__device__ __forceinline__ void stage_wt(const float* __restrict__ Wm,
                                         __half* sBT, int tid) {
#pragma unroll
    for (int i = 0; i < 64; i++) {
        int idx = tid + 256 * i;
        int k = idx >> 7, nn = idx & 127;
        sBT[nn * SRS + k] = __float2half(Wm[idx]);
    }
}

template <bool SCALE>
__device__ __forceinline__ void gemm_tile(const __half* sA, const __half* sBT,
                                          __half* __restrict__ out, int row0,
                                          int n, int tid,
                                          const float* __restrict__ dinv) {
    int lane = tid & 31, warp = tid >> 5;
    int g = lane >> 2, tg = lane & 3;
    int rb = warp * 16;

    float acc[16][4];
#pragma unroll
    for (int nt = 0; nt < 16; nt++)
#pragma unroll
        for (int q = 0; q < 4; q++) acc[nt][q] = 0.f;

#pragma unroll
    for (int ks = 0; ks < 8; ks++) {
        int k0 = ks * 16;
        uint32_t a0 = *(const uint32_t*)(sA + (rb + g) * SRS + k0 + tg * 2);
        uint32_t a1 = *(const uint32_t*)(sA + (rb + g + 8) * SRS + k0 + tg * 2);
        uint32_t a2 = *(const uint32_t*)(sA + (rb + g) * SRS + k0 + 8 + tg * 2);
        uint32_t a3 = *(const uint32_t*)(sA + (rb + g + 8) * SRS + k0 + 8 + tg * 2);
#pragma unroll
        for (int nt = 0; nt < 16; nt++) {
            uint32_t b0 = *(const uint32_t*)(sBT + (nt * 8 + g) * SRS + k0 + tg * 2);
            uint32_t b1 = *(const uint32_t*)(sBT + (nt * 8 + g) * SRS + k0 + 8 + tg * 2);
            asm volatile(
                "mma.sync.aligned.m16n8k16.row.col.f32.f16.f16.f32 "
                "{%0,%1,%2,%3},{%4,%5,%6,%7},{%8,%9},{%0,%1,%2,%3};"
                : "+f"(acc[nt][0]), "+f"(acc[nt][1]),
                  "+f"(acc[nt][2]), "+f"(acc[nt][3])
                : "r"(a0), "r"(a1), "r"(a2), "r"(a3), "r"(b0), "r"(b1));
        }
    }

    int r1 = row0 + rb + g;
    int r2 = r1 + 8;
    float dv1 = 1.f, dv2 = 1.f;
    if (SCALE) {
        dv1 = (r1 < n) ? dinv[r1] : 0.f;
        dv2 = (r2 < n) ? dinv[r2] : 0.f;
    }
#pragma unroll
    for (int nt = 0; nt < 16; nt++) {
        int c = nt * 8 + tg * 2;
        if (r1 < n) {
            __half2 h = __floats2half2_rn(acc[nt][0] * dv1, acc[nt][1] * dv1);
            *(__half2*)(out + r1 * 128 + c) = h;
        }
        if (r2 < n) {
            __half2 h = __floats2half2_rn(acc[nt][2] * dv2, acc[nt][3] * dv2);
            *(__half2*)(out + r2 * 128 + c) = h;
        }
    }
}

template <bool HALF_IN, bool SCALE>
__global__ void k_gemm_tc(const void* __restrict__ Ain, const float* __restrict__ Wm,
                          __half* __restrict__ out, const float* __restrict__ dinv,
                          int n) {
    extern __shared__ __half smh[];
    __half* sA = smh;
    __half* sBT = smh + 128 * SRS;
    int tid = threadIdx.x;
    int row0 = blockIdx.x * 128;

    stage_wt(Wm, sBT, tid);

    if (!HALF_IN) {
        const float4* A4 = (const float4*)Ain;
#pragma unroll
        for (int i = 0; i < 16; i++) {
            int idx = tid + 256 * i;
            int r = idx >> 5, c = (idx & 31) * 4;
            float4 v = make_float4(0.f, 0.f, 0.f, 0.f);
            if (row0 + r < n) v = A4[(row0 + r) * 32 + (idx & 31)];
            __half2 h0 = __floats2half2_rn(v.x, v.y);
            __half2 h1 = __floats2half2_rn(v.z, v.w);
            *(__half2*)(sA + r * SRS + c) = h0;
            *(__half2*)(sA + r * SRS + c + 2) = h1;
        }
    } else {
        const uint2* A2 = (const uint2*)Ain;
#pragma unroll
        for (int i = 0; i < 16; i++) {
            int idx = tid + 256 * i;
            int r = idx >> 5, c = (idx & 31) * 4;
            uint2 u = make_uint2(0u, 0u);
            if (row0 + r < n) u = A2[(row0 + r) * 32 + (idx & 31)];
            *(uint32_t*)(sA + r * SRS + c) = u.x;
            *(uint32_t*)(sA + r * SRS + c + 2) = u.y;
        }
    }
    __syncthreads();
    gemm_tile<SCALE>(sA, sBT, out, row0, n, tid, dinv);
}

// ---------------- aggregation: weightless row sums ----------------
// hs rows pre-scaled by dinv[src]: out[d] = dinv[d] * (sum_j hs[col_j] + hs[d])
__device__ __forceinline__ void add_row(uint2 u, float& ax, float& ay,
                                        float& az, float& aw) {
    float2 p0 = __half22float2(*reinterpret_cast<__half2*>(&u.x));
    float2 p1 = __half22float2(*reinterpret_cast<__half2*>(&u.y));
    ax += p0.x; ay += p0.y; az += p1.x; aw += p1.y;
}

__device__ __forceinline__ void agg_row(const uint2* __restrict__ hin, int node,
                                        int lane, float& ax, float& ay,
                                        float& az, float& aw) {
    int j = g_rowptr[node];
    int e = g_rowptr[node + 1];
    float di = g_dinv[node];
    {
        uint2 u = hin[node * 32 + lane];
        float2 f0 = __half22float2(*reinterpret_cast<__half2*>(&u.x));
        float2 f1 = __half22float2(*reinterpret_cast<__half2*>(&u.y));
        ax = f0.x; ay = f0.y; az = f1.x; aw = f1.y;
    }
    while ((j & 3) && j < e) {
        add_row(hin[g_col[j] * 32 + lane], ax, ay, az, aw);
        j++;
    }
    for (; j + 7 < e; j += 8) {
        int4 c0 = *(const int4*)&g_col[j];
        int4 c1 = *(const int4*)&g_col[j + 4];
        uint2 u0 = hin[c0.x * 32 + lane];
        uint2 u1 = hin[c0.y * 32 + lane];
        uint2 u2 = hin[c0.z * 32 + lane];
        uint2 u3 = hin[c0.w * 32 + lane];
        uint2 u4 = hin[c1.x * 32 + lane];
        uint2 u5 = hin[c1.y * 32 + lane];
        uint2 u6 = hin[c1.z * 32 + lane];
        uint2 u7 = hin[c1.w * 32 + lane];
        add_row(u0, ax, ay, az, aw);
        add_row(u1, ax, ay, az, aw);
        add_row(u2, ax, ay, az, aw);
        add_row(u3, ax, ay, az, aw);
        add_row(u4, ax, ay, az, aw);
        add_row(u5, ax, ay, az, aw);
        add_row(u6, ax, ay, az, aw);
        add_row(u7, ax, ay, az, aw);
    }
    if (j + 3 < e) {
        int4 c0 = *(const int4*)&g_col[j];
        uint2 u0 = hin[c0.x * 32 + lane];
        uint2 u1 = hin[c0.y * 32 + lane];
        uint2 u2 = hin[c0.z * 32 + lane];
        uint2 u3 = hin[c0.w * 32 + lane];
        add_row(u0, ax, ay, az, aw);
        add_row(u1, ax, ay, az, aw);
        add_row(u2, ax, ay, az, aw);
        add_row(u3, ax, ay, az, aw);
        j += 4;
    }
    for (; j < e; j++)
        add_row(hin[g_col[j] * 32 + lane], ax, ay, az, aw);
    ax *= di; ay *= di; az *= di; aw *= di;
}

// MODE 0: +bias, ReLU, fp16 out.   MODE 1: +bias, LayerNorm, fp32 out.
template <int MODE>
__global__ void k_agg(const uint2* __restrict__ hin, void* __restrict__ outp,
                      const float* __restrict__ bias, const float* __restrict__ gamma,
                      const float* __restrict__ beta) {
    int gw = (blockIdx.x * blockDim.x + threadIdx.x) >> 5;
    int lane = threadIdx.x & 31;
    if (gw >= NN) return;
    float ax, ay, az, aw;
    agg_row(hin, gw, lane, ax, ay, az, aw);

    float4 bv = ((const float4*)bias)[lane];
    ax += bv.x; ay += bv.y; az += bv.z; aw += bv.w;

    if (MODE == 0) {
        __half2 h0 = __floats2half2_rn(fmaxf(ax, 0.f), fmaxf(ay, 0.f));
        __half2 h1 = __floats2half2_rn(fmaxf(az, 0.f), fmaxf(aw, 0.f));
        uint2 u;
        u.x = *reinterpret_cast<unsigned*>(&h0);
        u.y = *reinterpret_cast<unsigned*>(&h1);
        ((uint2*)outp)[gw * 32 + lane] = u;
    } else {
        float sum = ax + ay + az + aw;
#pragma unroll
        for (int off = 16; off > 0; off >>= 1)
            sum += __shfl_xor_sync(0xFFFFFFFFu, sum, off);
        float mu = sum * (1.0f / 128.0f);
        float dx = ax - mu, dy = ay - mu, dz = az - mu, dw = aw - mu;
        float sq = dx * dx + dy * dy + dz * dz + dw * dw;
#pragma unroll
        for (int off = 16; off > 0; off >>= 1)
            sq += __shfl_xor_sync(0xFFFFFFFFu, sq, off);
        float rstd = rsqrtf(sq * (1.0f / 128.0f) + 1e-5f);
        float4 gv = ((const float4*)gamma)[lane];
        float4 btv = ((const float4*)beta)[lane];
        float4 o;
        o.x = dx * rstd * gv.x + btv.x;
        o.y = dy * rstd * gv.y + btv.y;
        o.z = dz * rstd * gv.z + btv.z;
        o.w = dw * rstd * gv.w + btv.w;
        ((float4*)outp)[gw * 32 + lane] = o;
    }
}

// ---------------- launch ----------------
extern "C" void kernel_launch(void* const* d_in, const int* in_sizes, int n_in,
                              void* d_out, int out_size) {
    const float* x   = (const float*)d_in[0];
    const void*  ei  = d_in[1];
    const float* W1  = (const float*)d_in[2];
    const float* b1  = (const float*)d_in[3];
    const float* W2  = (const float*)d_in[4];
    const float* b2  = (const float*)d_in[5];
    const float* gm  = (const float*)d_in[6];
    const float* bt  = (const float*)d_in[7];
    float*       out = (float*)d_out;

    int E = in_sizes[1] / 2;

    __half* h1buf; cudaGetSymbolAddress((void**)&h1buf, g_h1);
    __half* a1buf; cudaGetSymbolAddress((void**)&a1buf, g_a1);
    __half* h2buf; cudaGetSymbolAddress((void**)&h2buf, g_h2);
    float* dinvp;  cudaGetSymbolAddress((void**)&dinvp, g_dinv);

    const size_t smem_gemm = 2 * 128 * SRS * sizeof(__half);  // 69632 B
    static bool s_init_done = false;
    static cudaStream_t s_side = nullptr;
    static cudaEvent_t ev_fork = nullptr, ev_scan = nullptr, ev_join = nullptr;
    if (!s_init_done) {
        cudaFuncSetAttribute((void*)k_gemm_tc<false, false>,
                             cudaFuncAttributeMaxDynamicSharedMemorySize, (int)smem_gemm);
        cudaFuncSetAttribute((void*)k_gemm_tc<true, true>,
                             cudaFuncAttributeMaxDynamicSharedMemorySize, (int)smem_gemm);
        cudaStreamCreateWithFlags(&s_side, cudaStreamNonBlocking);
        cudaEventCreateWithFlags(&ev_fork, cudaEventDisableTiming);
        cudaEventCreateWithFlags(&ev_scan, cudaEventDisableTiming);
        cudaEventCreateWithFlags(&ev_join, cudaEventDisableTiming);
        s_init_done = true;
    }

    int ebl4 = (E / 4 + 255) / 256;
    int ebl = (E + 255) / 256;
    int cnt_blocks = ((E & 3) == 0) ? ebl4 : ebl;
    int agg_blocks = (NN * 32 + 255) / 256;
    int gemm_blocks = (NN + 127) / 128;
    int scale_blocks = (NN * 32 + 255) / 256;

    // ---- fork at t=0: gemm1 (unscaled) on side stream ----
    cudaEventRecord(ev_fork, 0);
    cudaStreamWaitEvent(s_side, ev_fork, 0);
    k_gemm_tc<false, false><<<gemm_blocks, 256, smem_gemm, s_side>>>(
        x, W1, h1buf, nullptr, NN);

    // ---- CSR build on main stream ----
    k_count<<<cnt_blocks, 256>>>(ei, E);
    k_reduce<<<NB_SCAN, 256>>>();
    k_scan_final<<<NB_SCAN, 256>>>();
    cudaEventRecord(ev_scan, 0);

    // side stream: once dinv ready (and gemm1 done), scale h1 in place
    cudaStreamWaitEvent(s_side, ev_scan, 0);
    k_scale<<<scale_blocks, 256, 0, s_side>>>(h1buf);
    cudaEventRecord(ev_join, s_side);

    k_scatter<<<cnt_blocks, 256>>>(ei, E);

    // ---- join side stream, then agg1 -> a1 ----
    cudaStreamWaitEvent(0, ev_join, 0);
    k_agg<0><<<agg_blocks, 256>>>((const uint2*)h1buf, a1buf, b1, nullptr, nullptr);

    // ---- gemm2: hs2 = dinv * (a1@W2) ----
    k_gemm_tc<true, true><<<gemm_blocks, 256, smem_gemm>>>(a1buf, W2, h2buf, dinvp, NN);

    // ---- agg2 + LayerNorm -> out ----
    k_agg<1><<<agg_blocks, 256>>>((const uint2*)h2buf, out, b2, gm, bt);
}

// round 16
// speedup vs baseline: 1.1469x; 1.0384x over previous
#include <cuda_runtime.h>
#include <cuda_fp16.h>
#include <cuda_bf16.h>
#include <cstdint>

// Problem constants
#define NN 100000
#define EE 1600000
#define DD 128
#define NB_SCAN ((NN + 255) / 256)   // 391 scan blocks

// ---------------- device scratch (no allocations allowed) ----------------
// g_deg/g_done zero on first use (CUDA zero-init), re-zeroed by k_scan_final.
__device__ int    g_done;
__device__ int    g_deg[NN];
__device__ int    g_rowptr[NN + 1];
__device__ int    g_cursor[NN];
__device__ int    g_psum[NB_SCAN];
__device__ __align__(16) int g_col[EE];   // edge payload: src node only
__device__ float  g_dinv[NN];
__device__ __half g_h1[NN * DD];     // GEMM1 output, then dinv-scaled in place
__device__ __half g_a1[NN * DD];     // layer-1 activation
__device__ __half g_h2[NN * DD];     // dinv-scaled GEMM2 output

// ---------------- helpers ----------------
__device__ __forceinline__ int load_idx(const void* ei, int pos, int is64) {
    if (is64) return (int)((const long long*)ei)[pos];
    return ((const int*)ei)[pos];
}

__device__ __forceinline__ int detect_is64(const int* ei32) {
    __shared__ int s_is64;
    if (threadIdx.x == 0) {
        int zeros = 0;
#pragma unroll
        for (int j = 0; j < 64; j++)
            if (ei32[2 * j + 1] == 0) zeros++;
        s_is64 = (zeros >= 60) ? 1 : 0;
    }
    __syncthreads();
    return s_is64;
}

// ---------------- graph-build kernels ----------------

// count degrees; return value unused -> REDG.
__global__ void k_count(const void* __restrict__ ei, int E) {
    int is64 = detect_is64((const int*)ei);
    int i = blockIdx.x * blockDim.x + threadIdx.x;
    if (!is64 && (E & 3) == 0) {
        int base = 4 * i;
        if (base >= E) return;
        const int4* dst4 = (const int4*)((const int*)ei + E);
        int4 d = dst4[i];
        if ((unsigned)d.x < (unsigned)NN) atomicAdd(&g_deg[d.x], 1);
        if ((unsigned)d.y < (unsigned)NN) atomicAdd(&g_deg[d.y], 1);
        if ((unsigned)d.z < (unsigned)NN) atomicAdd(&g_deg[d.z], 1);
        if ((unsigned)d.w < (unsigned)NN) atomicAdd(&g_deg[d.w], 1);
    } else {
        if (i >= E) return;
        int d = load_idx(ei, E + i, is64);
        if ((unsigned)d < (unsigned)NN) atomicAdd(&g_deg[d], 1);
    }
}

// Per-block sums -> g_psum[b]; LAST block scans g_psum (exclusive).
__global__ void k_reduce() {
    __shared__ int ws[8];
    __shared__ int s_last;
    int b = blockIdx.x, t = threadIdx.x;
    int lane = t & 31, w = t >> 5;
    int i = b * 256 + t;
    int v = (i < NN) ? g_deg[i] : 0;
#pragma unroll
    for (int off = 16; off > 0; off >>= 1)
        v += __shfl_xor_sync(0xFFFFFFFFu, v, off);
    if (lane == 0) ws[w] = v;
    __syncthreads();
    if (t == 0) {
        int s = 0;
#pragma unroll
        for (int k = 0; k < 8; k++) s += ws[k];
        g_psum[b] = s;
        __threadfence();
        int done = atomicAdd(&g_done, 1);
        s_last = (done == gridDim.x - 1) ? 1 : 0;
    }
    __syncthreads();
    if (!s_last) return;

    __shared__ int wsum[8];
    __shared__ int carry;
    if (t == 0) carry = 0;
    __syncthreads();
    for (int base = 0; base < NB_SCAN; base += 256) {
        int x = (base + t < NB_SCAN) ? g_psum[base + t] : 0;
        int s = x;
#pragma unroll
        for (int off = 1; off < 32; off <<= 1) {
            int u = __shfl_up_sync(0xFFFFFFFFu, s, off);
            if (lane >= off) s += u;
        }
        if (lane == 31) wsum[w] = s;
        __syncthreads();
        if (w == 0 && lane < 8) {
            int y = wsum[lane];
#pragma unroll
            for (int off = 1; off < 8; off <<= 1) {
                int u = __shfl_up_sync(0xFFu, y, off);
                if (lane >= off) y += u;
            }
            wsum[lane] = y;
        }
        __syncthreads();
        int pre = (w > 0) ? wsum[w - 1] : 0;
        int c = carry;
        if (base + t < NB_SCAN) g_psum[base + t] = c + pre + s - x;
        __syncthreads();
        if (t == 0) carry = c + wsum[7];
        __syncthreads();
    }
}

// Block-local scan + psum offset -> rowptr AND cursor; dinv fused;
// re-zero deg/done for next call.
__global__ void k_scan_final() {
    __shared__ int wsum[8];
    int b = blockIdx.x, t = threadIdx.x;
    int lane = t & 31, w = t >> 5;
    int i = b * 256 + t;
    int v = 0;
    if (i < NN) {
        v = g_deg[i];
        g_dinv[i] = rsqrtf((float)v + 1.0f);
        g_deg[i] = 0;
    }
    if (b == 0 && t == 0) g_done = 0;
    int s = v;
#pragma unroll
    for (int off = 1; off < 32; off <<= 1) {
        int u = __shfl_up_sync(0xFFFFFFFFu, s, off);
        if (lane >= off) s += u;
    }
    if (lane == 31) wsum[w] = s;
    __syncthreads();
    if (w == 0 && lane < 8) {
        int ws = wsum[lane];
#pragma unroll
        for (int off = 1; off < 8; off <<= 1) {
            int u = __shfl_up_sync(0xFFu, ws, off);
            if (lane >= off) ws += u;
        }
        wsum[lane] = ws;
    }
    __syncthreads();
    int pre = (w > 0) ? wsum[w - 1] : 0;
    int base = g_psum[b];
    if (i < NN) {
        g_rowptr[i + 1] = base + pre + s;
        g_cursor[i] = base + pre + s - v;
    }
    if (b == 0 && t == 0) g_rowptr[0] = 0;
}

// cursor scatter: one random atomic + one 4B random store per edge.
__device__ __forceinline__ void scatter_one(int s, int d) {
    if ((unsigned)s >= (unsigned)NN || (unsigned)d >= (unsigned)NN) return;
    int idx = atomicAdd(&g_cursor[d], 1);
    g_col[idx] = s;
}

__global__ void k_scatter(const void* __restrict__ ei, int E) {
    int is64 = detect_is64((const int*)ei);
    int i = blockIdx.x * blockDim.x + threadIdx.x;
    if (!is64 && (E & 3) == 0) {
        int base = 4 * i;
        if (base >= E) return;
        const int4* src4 = (const int4*)((const int*)ei);
        const int4* dst4 = (const int4*)((const int*)ei + E);
        int4 s = src4[i];
        int4 d = dst4[i];
        scatter_one(s.x, d.x);
        scatter_one(s.y, d.y);
        scatter_one(s.z, d.z);
        scatter_one(s.w, d.w);
    } else {
        if (i >= E) return;
        int s = load_idx(ei, i, is64);
        int d = load_idx(ei, E + i, is64);
        scatter_one(s, d);
    }
}

// scale h rows in place by dinv[row]: h[i,:] *= dinv[i].
__global__ void k_scale(__half* __restrict__ h) {
    int idx = blockIdx.x * blockDim.x + threadIdx.x;   // uint2 index
    if (idx >= NN * 32) return;
    float dv = g_dinv[idx >> 5];
    uint2 u = ((const uint2*)h)[idx];
    float2 f0 = __half22float2(*reinterpret_cast<__half2*>(&u.x));
    float2 f1 = __half22float2(*reinterpret_cast<__half2*>(&u.y));
    __half2 h0 = __floats2half2_rn(f0.x * dv, f0.y * dv);
    __half2 h1 = __floats2half2_rn(f1.x * dv, f1.y * dv);
    uint2 o;
    o.x = *reinterpret_cast<unsigned*>(&h0);
    o.y = *reinterpret_cast<unsigned*>(&h1);
    ((uint2*)h)[idx] = o;
}

// ---------------- tensor-core GEMM with pre-packed fragments ----------------
// smem layout (uint2 entries): entry(i, ks, tg) = i*36 + ks*4 + tg
//  sA2: i = tile row (0..127). entry = {halves(k0+2tg, +1), halves(k0+8+2tg, +1)}
//  sB2: i = output col (0..127). entry = {b0, b1} fragment pair for that col.
// The *36 stride makes lane pair-bank (4g+tg) mod 16 a permutation ->
// conflict-free LDS.64 in the mainloop.
#define FRAG_STRIDE 36
#define FRAG_ENTRIES (128 * FRAG_STRIDE)   // 4608 uint2 = 36864 B per operand

__device__ __forceinline__ void stage_w_packed(const float* __restrict__ Wm,
                                               uint2* sB2, int tid) {
#pragma unroll
    for (int i = 0; i < 16; i++) {
        int e = tid + 256 * i;          // 0..4095
        int nn = e & 127;               // output column
        int tgks = e >> 7;              // 0..31
        int tg = tgks >> 3, ks = tgks & 7;
        int k = ks * 16 + tg * 2;
        float f0 = Wm[k * 128 + nn];
        float f1 = Wm[(k + 1) * 128 + nn];
        float f2 = Wm[(k + 8) * 128 + nn];
        float f3 = Wm[(k + 9) * 128 + nn];
        __half2 h0 = __floats2half2_rn(f0, f1);
        __half2 h1 = __floats2half2_rn(f2, f3);
        uint2 val;
        val.x = *reinterpret_cast<unsigned*>(&h0);
        val.y = *reinterpret_cast<unsigned*>(&h1);
        sB2[nn * FRAG_STRIDE + ks * 4 + tg] = val;
    }
}

// store 4 halves (row r, cols c..c+3) into packed A layout
__device__ __forceinline__ void store_a_packed(uint32_t* sA2w, int r, int c,
                                               uint32_t h01, uint32_t h23) {
    int ks = c >> 4;
    int rem = c & 15;                // 0,4,8,12
    int tg0 = (rem & 7) >> 1;        // 0 or 2
    int y = (rem >= 8) ? 1 : 0;
    int e0 = r * FRAG_STRIDE + ks * 4 + tg0;
    sA2w[e0 * 2 + y] = h01;
    sA2w[(e0 + 1) * 2 + y] = h23;
}

template <bool SCALE>
__device__ __forceinline__ void gemm_tile(const uint2* sA2, const uint2* sB2,
                                          __half* __restrict__ out, int row0,
                                          int n, int tid,
                                          const float* __restrict__ dinv) {
    int lane = tid & 31, warp = tid >> 5;
    int g = lane >> 2, tg = lane & 3;
    int rb = warp * 16;

    float acc[16][4];
#pragma unroll
    for (int nt = 0; nt < 16; nt++)
#pragma unroll
        for (int q = 0; q < 4; q++) acc[nt][q] = 0.f;

#pragma unroll
    for (int ks = 0; ks < 8; ks++) {
        uint2 Ax = sA2[(rb + g) * FRAG_STRIDE + ks * 4 + tg];
        uint2 Ay = sA2[(rb + g + 8) * FRAG_STRIDE + ks * 4 + tg];
#pragma unroll
        for (int nt = 0; nt < 16; nt++) {
            uint2 B = sB2[(nt * 8 + g) * FRAG_STRIDE + ks * 4 + tg];
            asm volatile(
                "mma.sync.aligned.m16n8k16.row.col.f32.f16.f16.f32 "
                "{%0,%1,%2,%3},{%4,%5,%6,%7},{%8,%9},{%0,%1,%2,%3};"
                : "+f"(acc[nt][0]), "+f"(acc[nt][1]),
                  "+f"(acc[nt][2]), "+f"(acc[nt][3])
                : "r"(Ax.x), "r"(Ay.x), "r"(Ax.y), "r"(Ay.y),
                  "r"(B.x), "r"(B.y));
        }
    }

    int r1 = row0 + rb + g;
    int r2 = r1 + 8;
    float dv1 = 1.f, dv2 = 1.f;
    if (SCALE) {
        dv1 = (r1 < n) ? dinv[r1] : 0.f;
        dv2 = (r2 < n) ? dinv[r2] : 0.f;
    }
#pragma unroll
    for (int nt = 0; nt < 16; nt++) {
        int c = nt * 8 + tg * 2;
        if (r1 < n) {
            __half2 h = __floats2half2_rn(acc[nt][0] * dv1, acc[nt][1] * dv1);
            *(__half2*)(out + r1 * 128 + c) = h;
        }
        if (r2 < n) {
            __half2 h = __floats2half2_rn(acc[nt][2] * dv2, acc[nt][3] * dv2);
            *(__half2*)(out + r2 * 128 + c) = h;
        }
    }
}

template <bool HALF_IN, bool SCALE>
__global__ void k_gemm_tc(const void* __restrict__ Ain, const float* __restrict__ Wm,
                          __half* __restrict__ out, const float* __restrict__ dinv,
                          int n) {
    extern __shared__ uint2 smu[];
    uint2* sA2 = smu;                     // FRAG_ENTRIES
    uint2* sB2 = smu + FRAG_ENTRIES;      // FRAG_ENTRIES
    int tid = threadIdx.x;
    int row0 = blockIdx.x * 128;

    stage_w_packed(Wm, sB2, tid);

    uint32_t* sA2w = (uint32_t*)sA2;
    if (!HALF_IN) {
        const float4* A4 = (const float4*)Ain;
#pragma unroll
        for (int i = 0; i < 16; i++) {
            int idx = tid + 256 * i;
            int r = idx >> 5, q = idx & 31;
            float4 v = make_float4(0.f, 0.f, 0.f, 0.f);
            if (row0 + r < n) v = A4[(row0 + r) * 32 + q];
            __half2 h01 = __floats2half2_rn(v.x, v.y);
            __half2 h23 = __floats2half2_rn(v.z, v.w);
            store_a_packed(sA2w, r, q * 4,
                           *reinterpret_cast<unsigned*>(&h01),
                           *reinterpret_cast<unsigned*>(&h23));
        }
    } else {
        const uint2* A2 = (const uint2*)Ain;
#pragma unroll
        for (int i = 0; i < 16; i++) {
            int idx = tid + 256 * i;
            int r = idx >> 5, q = idx & 31;
            uint2 u = make_uint2(0u, 0u);
            if (row0 + r < n) u = A2[(row0 + r) * 32 + q];
            store_a_packed(sA2w, r, q * 4, u.x, u.y);
        }
    }
    __syncthreads();
    gemm_tile<SCALE>(sA2, sB2, out, row0, n, tid, dinv);
}

// ---------------- aggregation: weightless row sums ----------------
// hs rows pre-scaled by dinv[src]: out[d] = dinv[d] * (sum_j hs[col_j] + hs[d])
__device__ __forceinline__ void add_row(uint2 u, float& ax, float& ay,
                                        float& az, float& aw) {
    float2 p0 = __half22float2(*reinterpret_cast<__half2*>(&u.x));
    float2 p1 = __half22float2(*reinterpret_cast<__half2*>(&u.y));
    ax += p0.x; ay += p0.y; az += p1.x; aw += p1.y;
}

__device__ __forceinline__ void agg_row(const uint2* __restrict__ hin, int node,
                                        int lane, float& ax, float& ay,
                                        float& az, float& aw) {
    int j = g_rowptr[node];
    int e = g_rowptr[node + 1];
    float di = g_dinv[node];
    {
        uint2 u = hin[node * 32 + lane];
        float2 f0 = __half22float2(*reinterpret_cast<__half2*>(&u.x));
        float2 f1 = __half22float2(*reinterpret_cast<__half2*>(&u.y));
        ax = f0.x; ay = f0.y; az = f1.x; aw = f1.y;
    }
    while ((j & 3) && j < e) {
        add_row(hin[g_col[j] * 32 + lane], ax, ay, az, aw);
        j++;
    }
    for (; j + 7 < e; j += 8) {
        int4 c0 = *(const int4*)&g_col[j];
        int4 c1 = *(const int4*)&g_col[j + 4];
        uint2 u0 = hin[c0.x * 32 + lane];
        uint2 u1 = hin[c0.y * 32 + lane];
        uint2 u2 = hin[c0.z * 32 + lane];
        uint2 u3 = hin[c0.w * 32 + lane];
        uint2 u4 = hin[c1.x * 32 + lane];
        uint2 u5 = hin[c1.y * 32 + lane];
        uint2 u6 = hin[c1.z * 32 + lane];
        uint2 u7 = hin[c1.w * 32 + lane];
        add_row(u0, ax, ay, az, aw);
        add_row(u1, ax, ay, az, aw);
        add_row(u2, ax, ay, az, aw);
        add_row(u3, ax, ay, az, aw);
        add_row(u4, ax, ay, az, aw);
        add_row(u5, ax, ay, az, aw);
        add_row(u6, ax, ay, az, aw);
        add_row(u7, ax, ay, az, aw);
    }
    if (j + 3 < e) {
        int4 c0 = *(const int4*)&g_col[j];
        uint2 u0 = hin[c0.x * 32 + lane];
        uint2 u1 = hin[c0.y * 32 + lane];
        uint2 u2 = hin[c0.z * 32 + lane];
        uint2 u3 = hin[c0.w * 32 + lane];
        add_row(u0, ax, ay, az, aw);
        add_row(u1, ax, ay, az, aw);
        add_row(u2, ax, ay, az, aw);
        add_row(u3, ax, ay, az, aw);
        j += 4;
    }
    for (; j < e; j++)
        add_row(hin[g_col[j] * 32 + lane], ax, ay, az, aw);
    ax *= di; ay *= di; az *= di; aw *= di;
}

// MODE 0: +bias, ReLU, fp16 out.   MODE 1: +bias, LayerNorm, fp32 out.
template <int MODE>
__global__ void k_agg(const uint2* __restrict__ hin, void* __restrict__ outp,
                      const float* __restrict__ bias, const float* __restrict__ gamma,
                      const float* __restrict__ beta) {
    int gw = (blockIdx.x * blockDim.x + threadIdx.x) >> 5;
    int lane = threadIdx.x & 31;
    if (gw >= NN) return;
    float ax, ay, az, aw;
    agg_row(hin, gw, lane, ax, ay, az, aw);

    float4 bv = ((const float4*)bias)[lane];
    ax += bv.x; ay += bv.y; az += bv.z; aw += bv.w;

    if (MODE == 0) {
        __half2 h0 = __floats2half2_rn(fmaxf(ax, 0.f), fmaxf(ay, 0.f));
        __half2 h1 = __floats2half2_rn(fmaxf(az, 0.f), fmaxf(aw, 0.f));
        uint2 u;
        u.x = *reinterpret_cast<unsigned*>(&h0);
        u.y = *reinterpret_cast<unsigned*>(&h1);
        ((uint2*)outp)[gw * 32 + lane] = u;
    } else {
        float sum = ax + ay + az + aw;
#pragma unroll
        for (int off = 16; off > 0; off >>= 1)
            sum += __shfl_xor_sync(0xFFFFFFFFu, sum, off);
        float mu = sum * (1.0f / 128.0f);
        float dx = ax - mu, dy = ay - mu, dz = az - mu, dw = aw - mu;
        float sq = dx * dx + dy * dy + dz * dz + dw * dw;
#pragma unroll
        for (int off = 16; off > 0; off >>= 1)
            sq += __shfl_xor_sync(0xFFFFFFFFu, sq, off);
        float rstd = rsqrtf(sq * (1.0f / 128.0f) + 1e-5f);
        float4 gv = ((const float4*)gamma)[lane];
        float4 btv = ((const float4*)beta)[lane];
        float4 o;
        o.x = dx * rstd * gv.x + btv.x;
        o.y = dy * rstd * gv.y + btv.y;
        o.z = dz * rstd * gv.z + btv.z;
        o.w = dw * rstd * gv.w + btv.w;
        ((float4*)outp)[gw * 32 + lane] = o;
    }
}

// ---------------- launch ----------------
extern "C" void kernel_launch(void* const* d_in, const int* in_sizes, int n_in,
                              void* d_out, int out_size) {
    const float* x   = (const float*)d_in[0];
    const void*  ei  = d_in[1];
    const float* W1  = (const float*)d_in[2];
    const float* b1  = (const float*)d_in[3];
    const float* W2  = (const float*)d_in[4];
    const float* b2  = (const float*)d_in[5];
    const float* gm  = (const float*)d_in[6];
    const float* bt  = (const float*)d_in[7];
    float*       out = (float*)d_out;

    int E = in_sizes[1] / 2;

    __half* h1buf; cudaGetSymbolAddress((void**)&h1buf, g_h1);
    __half* a1buf; cudaGetSymbolAddress((void**)&a1buf, g_a1);
    __half* h2buf; cudaGetSymbolAddress((void**)&h2buf, g_h2);
    float* dinvp;  cudaGetSymbolAddress((void**)&dinvp, g_dinv);

    const size_t smem_gemm = 2 * FRAG_ENTRIES * sizeof(uint2);  // 73728 B
    static bool s_init_done = false;
    static cudaStream_t s_side = nullptr;
    static cudaEvent_t ev_fork = nullptr, ev_scan = nullptr, ev_join = nullptr;
    if (!s_init_done) {
        cudaFuncSetAttribute((void*)k_gemm_tc<false, false>,
                             cudaFuncAttributeMaxDynamicSharedMemorySize, (int)smem_gemm);
        cudaFuncSetAttribute((void*)k_gemm_tc<true, true>,
                             cudaFuncAttributeMaxDynamicSharedMemorySize, (int)smem_gemm);
        cudaStreamCreateWithFlags(&s_side, cudaStreamNonBlocking);
        cudaEventCreateWithFlags(&ev_fork, cudaEventDisableTiming);
        cudaEventCreateWithFlags(&ev_scan, cudaEventDisableTiming);
        cudaEventCreateWithFlags(&ev_join, cudaEventDisableTiming);
        s_init_done = true;
    }

    int ebl4 = (E / 4 + 255) / 256;
    int ebl = (E + 255) / 256;
    int cnt_blocks = ((E & 3) == 0) ? ebl4 : ebl;
    int agg_blocks = (NN * 32 + 255) / 256;
    int gemm_blocks = (NN + 127) / 128;
    int scale_blocks = (NN * 32 + 255) / 256;

    // ---- fork at t=0: gemm1 (unscaled) on side stream ----
    cudaEventRecord(ev_fork, 0);
    cudaStreamWaitEvent(s_side, ev_fork, 0);
    k_gemm_tc<false, false><<<gemm_blocks, 256, smem_gemm, s_side>>>(
        x, W1, h1buf, nullptr, NN);

    // ---- CSR build on main stream ----
    k_count<<<cnt_blocks, 256>>>(ei, E);
    k_reduce<<<NB_SCAN, 256>>>();
    k_scan_final<<<NB_SCAN, 256>>>();
    cudaEventRecord(ev_scan, 0);

    // side stream: once dinv ready (and gemm1 done), scale h1 in place
    cudaStreamWaitEvent(s_side, ev_scan, 0);
    k_scale<<<scale_blocks, 256, 0, s_side>>>(h1buf);
    cudaEventRecord(ev_join, s_side);

    k_scatter<<<cnt_blocks, 256>>>(ei, E);

    // ---- join side stream, then agg1 -> a1 ----
    cudaStreamWaitEvent(0, ev_join, 0);
    k_agg<0><<<agg_blocks, 256>>>((const uint2*)h1buf, a1buf, b1, nullptr, nullptr);

    // ---- gemm2: hs2 = dinv * (a1@W2) ----
    k_gemm_tc<true, true><<<gemm_blocks, 256, smem_gemm>>>(a1buf, W2, h2buf, dinvp, NN);

    // ---- agg2 + LayerNorm -> out ----
    k_agg<1><<<agg_blocks, 256>>>((const uint2*)h2buf, out, b2, gm, bt);
}